// round 2
// baseline (speedup 1.0000x reference)
#include <cuda_runtime.h>
#include <math.h>
#include <float.h>

#define S_  4096
#define H_  1024
#define NH_ 2
#define HD_ 512
#define DS_ 64

// ---------------- scratch (device globals; no allocations allowed) ----------
__device__ float g_semb[H_];
__device__ float g_kvin[(size_t)S_ * H_];
__device__ float g_Q[(size_t)S_ * H_];
__device__ float g_K[(size_t)S_ * H_];
__device__ float g_V[(size_t)S_ * H_];
__device__ float g_ctx[(size_t)S_ * H_];
__device__ float g_logits[(size_t)S_ * S_];
__device__ float g_out[(size_t)S_ * H_];
__device__ unsigned char g_maskb[S_];

// ---------------- mask canonicalization --------------------------------------
// The harness may materialize the bool mask as int32 (4 bytes/elem) or as raw
// bool (1 byte/elem). Detect device-side: any nonzero byte at offset %4 != 0
// implies the 1-byte layout (an int32 array of 0/1 has nonzero bytes only at
// offsets %4 == 0). Single block; branch chosen before any wide reads.
__global__ void mask_prep_kernel(const unsigned char* __restrict__ mraw) {
    __shared__ int flag;
    if (threadIdx.x == 0) flag = 0;
    __syncthreads();
    int local = 0;
    for (int i = threadIdx.x; i < S_; i += blockDim.x)
        if ((i & 3) && mraw[i]) local = 1;
    if (local) atomicOr(&flag, 1);
    __syncthreads();
    if (flag) {  // 1-byte bool layout
        for (int i = threadIdx.x; i < S_; i += blockDim.x)
            g_maskb[i] = mraw[i] ? 1 : 0;
    } else {     // int32 layout
        const int* mi = (const int*)mraw;
        for (int i = threadIdx.x; i < S_; i += blockDim.x)
            g_maskb[i] = mi[i] ? 1 : 0;
    }
}

// ---------------- small kernels ---------------------------------------------
__global__ void semb_kernel(const float* __restrict__ Ws,
                            const float* __restrict__ sd,
                            const float* __restrict__ bsv) {
    int j = blockIdx.x * blockDim.x + threadIdx.x;
    if (j < H_) {
        float acc = bsv[j];
#pragma unroll
        for (int i = 0; i < DS_; i++) acc = fmaf(Ws[j * DS_ + i], sd[i], acc);
        g_semb[j] = acc;
    }
}

__global__ void kvin_kernel(const float* __restrict__ inp) {
    int idx = blockIdx.x * blockDim.x + threadIdx.x;
    g_kvin[idx] = inp[idx] + g_semb[idx & (H_ - 1)];
}

// ---------------- SGEMM: C[M,N] = alpha * A[M,K] * op(B) --------------------
// BT=true : B is [N,K] row-major (NT gemm, both K-major)
// BT=false: B is [K,N] row-major (NN gemm)
// mask != nullptr: columns with mask[col]==0 are forced to -FLT_MAX (finfo.min)
template <bool BT>
__launch_bounds__(256, 2)
__global__ void sgemm_kernel(const float* __restrict__ A, int lda,
                             const float* __restrict__ B, int ldb,
                             float* __restrict__ C, int ldc,
                             int K, float alpha,
                             const unsigned char* __restrict__ mask) {
    __shared__ float As[8][128];
    __shared__ float Bs[8][128];

    const int tid  = threadIdx.x;
    const int row0 = blockIdx.y * 128;
    const int col0 = blockIdx.x * 128;

    const int ar = tid >> 1;          // 0..127
    const int ak = (tid & 1) * 4;     // 0 or 4
    const int rb = (tid >> 4) * 8;    // micro-tile row base
    const int cb = (tid & 15) * 8;    // micro-tile col base

    float acc[8][8];
#pragma unroll
    for (int i = 0; i < 8; i++)
#pragma unroll
        for (int j = 0; j < 8; j++) acc[i][j] = 0.f;

    for (int k0 = 0; k0 < K; k0 += 8) {
        float4 av = *reinterpret_cast<const float4*>(
            &A[(size_t)(row0 + ar) * lda + k0 + ak]);
        As[ak + 0][ar] = av.x; As[ak + 1][ar] = av.y;
        As[ak + 2][ar] = av.z; As[ak + 3][ar] = av.w;

        if (BT) {
            float4 bv = *reinterpret_cast<const float4*>(
                &B[(size_t)(col0 + ar) * ldb + k0 + ak]);
            Bs[ak + 0][ar] = bv.x; Bs[ak + 1][ar] = bv.y;
            Bs[ak + 2][ar] = bv.z; Bs[ak + 3][ar] = bv.w;
        } else {
            const int bkk = tid >> 5;        // 0..7
            const int bn  = (tid & 31) * 4;  // 0..124
            float4 bv = *reinterpret_cast<const float4*>(
                &B[(size_t)(k0 + bkk) * ldb + col0 + bn]);
            *reinterpret_cast<float4*>(&Bs[bkk][bn]) = bv;
        }
        __syncthreads();

#pragma unroll
        for (int kk = 0; kk < 8; kk++) {
            float a[8], b[8];
            *reinterpret_cast<float4*>(&a[0]) = *reinterpret_cast<const float4*>(&As[kk][rb]);
            *reinterpret_cast<float4*>(&a[4]) = *reinterpret_cast<const float4*>(&As[kk][rb + 4]);
            *reinterpret_cast<float4*>(&b[0]) = *reinterpret_cast<const float4*>(&Bs[kk][cb]);
            *reinterpret_cast<float4*>(&b[4]) = *reinterpret_cast<const float4*>(&Bs[kk][cb + 4]);
#pragma unroll
            for (int i = 0; i < 8; i++)
#pragma unroll
                for (int j = 0; j < 8; j++)
                    acc[i][j] = fmaf(a[i], b[j], acc[i][j]);
        }
        __syncthreads();
    }

#pragma unroll
    for (int i = 0; i < 8; i++) {
#pragma unroll
        for (int j = 0; j < 8; j++) {
            int c   = col0 + cb + j;
            float v = acc[i][j] * alpha;
            if (mask != nullptr && mask[c] == 0) v = -FLT_MAX;
            C[(size_t)(row0 + rb + i) * ldc + c] = v;
        }
    }
}

// ---------------- reductions -------------------------------------------------
__device__ __forceinline__ float block_reduce_max(float v, float* sh) {
    int tid = threadIdx.x;
#pragma unroll
    for (int o = 16; o > 0; o >>= 1) v = fmaxf(v, __shfl_xor_sync(0xffffffffu, v, o));
    if ((tid & 31) == 0) sh[tid >> 5] = v;
    __syncthreads();
    if (tid < 32) {
        float x = (tid < 8) ? sh[tid] : -FLT_MAX;
#pragma unroll
        for (int o = 4; o > 0; o >>= 1) x = fmaxf(x, __shfl_xor_sync(0xffffffffu, x, o));
        if (tid == 0) sh[0] = x;
    }
    __syncthreads();
    float r = sh[0];
    __syncthreads();
    return r;
}

__device__ __forceinline__ float block_reduce_sum(float v, float* sh) {
    int tid = threadIdx.x;
#pragma unroll
    for (int o = 16; o > 0; o >>= 1) v += __shfl_xor_sync(0xffffffffu, v, o);
    if ((tid & 31) == 0) sh[tid >> 5] = v;
    __syncthreads();
    if (tid < 32) {
        float x = (tid < 8) ? sh[tid] : 0.f;
#pragma unroll
        for (int o = 4; o > 0; o >>= 1) x += __shfl_xor_sync(0xffffffffu, x, o);
        if (tid == 0) sh[0] = x;
    }
    __syncthreads();
    float r = sh[0];
    __syncthreads();
    return r;
}

// ---------------- softmax over rows of g_logits ------------------------------
__global__ void softmax_kernel() {
    __shared__ float sh[8];
    const int q  = blockIdx.x;
    float* row   = g_logits + (size_t)q * S_;
    const int tid = threadIdx.x;

    float m = -FLT_MAX;
    for (int i = tid; i < S_; i += 256) m = fmaxf(m, row[i]);
    m = block_reduce_max(m, sh);

    float sum = 0.f;
    for (int i = tid; i < S_; i += 256) {
        float x = row[i];
        float e = (x == -FLT_MAX) ? 0.f : __expf(x - m);
        row[i]  = e;
        sum    += e;
    }
    sum = block_reduce_sum(sum, sh);

    float inv = 1.f / sum;
    for (int i = tid; i < S_; i += 256) row[i] *= inv;
}

// ---------------- residual + LayerNorm ---------------------------------------
__global__ void ln_kernel(const float* __restrict__ inp,
                          const float* __restrict__ lnw,
                          const float* __restrict__ lnb,
                          float* __restrict__ out) {
    __shared__ float sh[8];
    const int s   = blockIdx.x;
    const int tid = threadIdx.x;
    const float* o = g_out + (size_t)s * H_;
    const float* x = inp   + (size_t)s * H_;

    float sum = 0.f, sq = 0.f;
    for (int i = tid; i < H_; i += 256) {
        float r = o[i] + x[i];
        sum += r;
        sq  += r * r;
    }
    sum = block_reduce_sum(sum, sh);
    sq  = block_reduce_sum(sq, sh);

    float mu  = sum * (1.f / H_);
    float var = sq * (1.f / H_) - mu * mu;
    float inv = rsqrtf(var + 1e-5f);

    for (int i = tid; i < H_; i += 256) {
        float r = o[i] + x[i];
        out[(size_t)s * H_ + i] = (r - mu) * inv * lnw[i] + lnb[i];
    }
}

// ---------------- launch ------------------------------------------------------
extern "C" void kernel_launch(void* const* d_in, const int* in_sizes, int n_in,
                              void* d_out, int out_size) {
    const float*         inputs = (const float*)d_in[0];
    const float*         sd     = (const float*)d_in[1];
    const unsigned char* mraw   = (const unsigned char*)d_in[2];
    const float*         Wq     = (const float*)d_in[3];
    const float*         Wk     = (const float*)d_in[4];
    const float*         Wv     = (const float*)d_in[5];
    const float*         Wo     = (const float*)d_in[6];
    const float*         Ws     = (const float*)d_in[7];
    const float*         bsv    = (const float*)d_in[8];
    const float*         lnw    = (const float*)d_in[9];
    const float*         lnb    = (const float*)d_in[10];
    float*               out    = (float*)d_out;

    float *pQ, *pK, *pV, *pKV, *pCtx, *pLog, *pOut;
    unsigned char* pMask;
    cudaGetSymbolAddress((void**)&pQ,   g_Q);
    cudaGetSymbolAddress((void**)&pK,   g_K);
    cudaGetSymbolAddress((void**)&pV,   g_V);
    cudaGetSymbolAddress((void**)&pKV,  g_kvin);
    cudaGetSymbolAddress((void**)&pCtx, g_ctx);
    cudaGetSymbolAddress((void**)&pLog, g_logits);
    cudaGetSymbolAddress((void**)&pOut, g_out);
    cudaGetSymbolAddress((void**)&pMask, g_maskb);

    const float inv_sqrt_hd = 1.0f / sqrtf((float)HD_);

    // 0. canonicalize mask dtype (int32 vs bool bytes)
    mask_prep_kernel<<<1, 256>>>(mraw);

    // 1. static embedding + kv input
    semb_kernel<<<4, 256>>>(Ws, sd, bsv);
    kvin_kernel<<<(S_ * H_) / 256, 256>>>(inputs);

    // 2. projections (NT gemms)
    dim3 gp(H_ / 128, S_ / 128);
    sgemm_kernel<true><<<gp, 256>>>(inputs, H_, Wq, H_, pQ, H_, H_, 1.0f, nullptr);
    sgemm_kernel<true><<<gp, 256>>>(pKV,    H_, Wk, H_, pK, H_, H_, 1.0f, nullptr);
    sgemm_kernel<true><<<gp, 256>>>(pKV,    H_, Wv, H_, pV, H_, H_, 1.0f, nullptr);

    // 3. attention, head by head (logits scratch reused)
    for (int h = 0; h < NH_; h++) {
        const unsigned char* m = (h == 0) ? pMask : nullptr;
        dim3 gl(S_ / 128, S_ / 128);
        sgemm_kernel<true><<<gl, 256>>>(pQ + h * HD_, H_,
                                        pK + h * HD_, H_,
                                        pLog, S_, HD_, inv_sqrt_hd, m);
        softmax_kernel<<<S_, 256>>>();
        dim3 gv(HD_ / 128, S_ / 128);
        sgemm_kernel<false><<<gv, 256>>>(pLog, S_,
                                         pV + h * HD_, H_,
                                         pCtx + h * HD_, H_, S_, 1.0f, nullptr);
    }

    // 4. output projection + residual LayerNorm
    sgemm_kernel<true><<<gp, 256>>>(pCtx, H_, Wo, H_, pOut, H_, H_, 1.0f, nullptr);
    ln_kernel<<<S_, 256>>>(inputs, lnw, lnb, out);
}

// round 4
// speedup vs baseline: 2.9157x; 2.9157x over previous
#include <cuda_runtime.h>
#include <cuda_bf16.h>
#include <math.h>
#include <float.h>
#include <stdint.h>

#define S_  4096
#define H_  1024
#define NH_ 2
#define HD_ 512
#define DS_ 64
#define K3  (3 * H_)    // 3072
#define KQK (3 * HD_)   // 1536
#define KPV (3 * S_)    // 12288

// ---------------- scratch (device globals; no allocations allowed) ----------
__device__ float g_semb[H_];
__device__ float g_kvin[(size_t)S_ * H_];
__device__ float g_Q[(size_t)S_ * H_];
__device__ float g_K[(size_t)S_ * H_];
__device__ float g_V[(size_t)S_ * H_];
__device__ float g_ctx[(size_t)S_ * H_];
__device__ float g_logits[(size_t)S_ * S_];
__device__ float g_out[(size_t)S_ * H_];
__device__ unsigned char g_maskb[S_];

__device__ __nv_bfloat16 g_ins_s [(size_t)S_ * K3];
__device__ __nv_bfloat16 g_kvin_s[(size_t)S_ * K3];
__device__ __nv_bfloat16 g_Wq_s[(size_t)H_ * K3];
__device__ __nv_bfloat16 g_Wk_s[(size_t)H_ * K3];
__device__ __nv_bfloat16 g_Wv_s[(size_t)H_ * K3];
__device__ __nv_bfloat16 g_Wo_s[(size_t)H_ * K3];
__device__ __nv_bfloat16 g_Qs[(size_t)S_ * NH_ * KQK];
__device__ __nv_bfloat16 g_Ks[(size_t)S_ * NH_ * KQK];
__device__ __nv_bfloat16 g_Ps[(size_t)S_ * KPV];
__device__ __nv_bfloat16 g_Vts[(size_t)NH_ * HD_ * KPV];
__device__ __nv_bfloat16 g_ctxs[(size_t)S_ * K3];

// ===================== helpers ===============================================
__device__ __forceinline__ uint32_t smem_u32(const void* p) {
    uint32_t a;
    asm("{ .reg .u64 t; cvta.to.shared.u64 t, %1; cvt.u32.u64 %0, t; }" : "=r"(a) : "l"(p));
    return a;
}
#define CP_ASYNC16(dst, src) \
    asm volatile("cp.async.cg.shared.global [%0], [%1], 16;" :: "r"(dst), "l"(src))
#define CP_COMMIT() asm volatile("cp.async.commit_group;")
#define CP_WAIT(n)  asm volatile("cp.async.wait_group %0;" :: "n"(n))

__device__ __forceinline__ void ldsm_x4(uint32_t& r0, uint32_t& r1, uint32_t& r2, uint32_t& r3,
                                        uint32_t addr) {
    asm volatile("ldmatrix.sync.aligned.m8n8.x4.shared.b16 {%0,%1,%2,%3}, [%4];"
                 : "=r"(r0), "=r"(r1), "=r"(r2), "=r"(r3) : "r"(addr));
}
__device__ __forceinline__ void mma_16816(float* c, const uint32_t* a, uint32_t b0, uint32_t b1) {
    asm volatile("mma.sync.aligned.m16n8k16.row.col.f32.bf16.bf16.f32 "
                 "{%0,%1,%2,%3}, {%4,%5,%6,%7}, {%8,%9}, {%0,%1,%2,%3};"
                 : "+f"(c[0]), "+f"(c[1]), "+f"(c[2]), "+f"(c[3])
                 : "r"(a[0]), "r"(a[1]), "r"(a[2]), "r"(a[3]), "r"(b0), "r"(b1));
}

// smem tile: 128 rows x 64 bf16 (128B/row), XOR swizzle on 16B chunks
__device__ __forceinline__ uint32_t toff(int r, int c8) {
    return (uint32_t)(r * 128 + ((c8 ^ (r & 7)) << 4));
}

// ===================== bf16 HMMA GEMM ========================================
// C[M,N] (fp32) = alpha * A[M,Kp](bf16,K-major) . B[N,Kp]^T(bf16,K-major)
// Kp % 64 == 0. CTA tile 128x128, BK=64, double-buffered cp.async.
#define GEMM_SMEM (2 * 32768)

__global__ __launch_bounds__(256, 2)
void bf16_gemm_kernel(const __nv_bfloat16* __restrict__ A, int lda,
                      const __nv_bfloat16* __restrict__ B, int ldb,
                      float* __restrict__ C, int ldc,
                      int Kp, float alpha,
                      const unsigned char* __restrict__ mask) {
    extern __shared__ char smem[];
    const uint32_t sb = smem_u32(smem);
    const int tid  = threadIdx.x, lane = tid & 31, wid = tid >> 5;
    const int row0 = blockIdx.y * 128, col0 = blockIdx.x * 128;
    const int wm = wid & 3, wn = wid >> 2;          // 4x2 warp grid
    const int m_base = wm * 32, n_base = wn * 64;   // 32x64 per warp

    const uint32_t bufA[2] = {sb, sb + 32768};
    const uint32_t bufB[2] = {sb + 16384, sb + 32768 + 16384};

    // cp.async mapping: idx -> (row, c8)
    const int lr = tid >> 3, lc = tid & 7;          // 32 rows per pass, 8 chunks

    // ldmatrix lane patterns
    const int g = lane >> 3, ri = lane & 7;
    const int a_r = ri + ((g & 1) << 3), a_c = g >> 1;        // A: m16 x k16
    const int b_r = ri + ((g >> 1) << 3), b_c = g & 1;        // B: n16 x k16

    float acc[2][8][4];
#pragma unroll
    for (int i = 0; i < 2; i++)
#pragma unroll
        for (int j = 0; j < 8; j++)
#pragma unroll
            for (int k = 0; k < 4; k++) acc[i][j][k] = 0.f;

    const int NS = Kp >> 6;

    // stage loader
    auto load_stage = [&](int s) {
        const int k0 = s << 6;
        const uint32_t ba = bufA[s & 1], bb = bufB[s & 1];
#pragma unroll
        for (int i = 0; i < 4; i++) {
            int r = lr + 32 * i;
            const __nv_bfloat16* gA = A + (size_t)(row0 + r) * lda + k0 + lc * 8;
            const __nv_bfloat16* gB = B + (size_t)(col0 + r) * ldb + k0 + lc * 8;
            CP_ASYNC16(ba + toff(r, lc), gA);
            CP_ASYNC16(bb + toff(r, lc), gB);
        }
        CP_COMMIT();
    };

    load_stage(0);

    for (int s = 0; s < NS; s++) {
        if (s + 1 < NS) { load_stage(s + 1); CP_WAIT(1); }
        else            { CP_WAIT(0); }
        __syncthreads();

        const uint32_t ba = bufA[s & 1], bb = bufB[s & 1];
#pragma unroll
        for (int ks = 0; ks < 4; ks++) {
            const int c8k = ks << 1;
            uint32_t afr[2][4];
#pragma unroll
            for (int mi = 0; mi < 2; mi++)
                ldsm_x4(afr[mi][0], afr[mi][1], afr[mi][2], afr[mi][3],
                        ba + toff(m_base + mi * 16 + a_r, c8k + a_c));
            uint32_t bfr[4][4];
#pragma unroll
            for (int p = 0; p < 4; p++)
                ldsm_x4(bfr[p][0], bfr[p][1], bfr[p][2], bfr[p][3],
                        bb + toff(n_base + p * 16 + b_r, c8k + b_c));
#pragma unroll
            for (int mi = 0; mi < 2; mi++)
#pragma unroll
                for (int nj = 0; nj < 8; nj++) {
                    const uint32_t* bp = bfr[nj >> 1];
                    if (nj & 1) mma_16816(acc[mi][nj], afr[mi], bp[2], bp[3]);
                    else        mma_16816(acc[mi][nj], afr[mi], bp[0], bp[1]);
                }
        }
        __syncthreads();
    }

    // epilogue: fused alpha + mask, float2 stores
    const int er = lane >> 2, ec = (lane & 3) << 1;
#pragma unroll
    for (int mi = 0; mi < 2; mi++) {
#pragma unroll
        for (int nj = 0; nj < 8; nj++) {
            int row = row0 + m_base + mi * 16 + er;
            int col = col0 + n_base + nj * 8 + ec;
            float2 v0, v1;
            v0.x = acc[mi][nj][0] * alpha; v0.y = acc[mi][nj][1] * alpha;
            v1.x = acc[mi][nj][2] * alpha; v1.y = acc[mi][nj][3] * alpha;
            if (mask != nullptr) {
                unsigned char m0 = mask[col], m1 = mask[col + 1];
                if (!m0) { v0.x = -FLT_MAX; v1.x = -FLT_MAX; }
                if (!m1) { v0.y = -FLT_MAX; v1.y = -FLT_MAX; }
            }
            *reinterpret_cast<float2*>(C + (size_t)row * ldc + col) = v0;
            *reinterpret_cast<float2*>(C + (size_t)(row + 8) * ldc + col) = v1;
        }
    }
}

// ===================== split kernels =========================================
__device__ __forceinline__ void split2(float x, __nv_bfloat16& hi, __nv_bfloat16& lo) {
    hi = __float2bfloat16(x);
    lo = __float2bfloat16(x - __bfloat162float(hi));
}

// variant 0 (A side): [hi | lo | hi] ; variant 1 (B side): [hi | hi | lo]
__global__ void split_plain_kernel(const float* __restrict__ src, __nv_bfloat16* __restrict__ dst,
                                   int K, int variant) {
    size_t i = (size_t)blockIdx.x * blockDim.x + threadIdx.x;
    int row = (int)(i / K), col = (int)(i % K);
    __nv_bfloat16 hi, lo;
    split2(src[i], hi, lo);
    size_t base = (size_t)row * (3 * (size_t)K);
    if (variant == 0) {
        dst[base + col] = hi; dst[base + K + col] = lo; dst[base + 2 * (size_t)K + col] = hi;
    } else {
        dst[base + col] = hi; dst[base + K + col] = hi; dst[base + 2 * (size_t)K + col] = lo;
    }
}

__global__ void split_heads_kernel(const float* __restrict__ src, __nv_bfloat16* __restrict__ dst,
                                   int variant) {
    size_t i = (size_t)blockIdx.x * blockDim.x + threadIdx.x;
    int row = (int)(i >> 10), j = (int)(i & (H_ - 1));
    int h = j >> 9, jh = j & (HD_ - 1);
    __nv_bfloat16 hi, lo;
    split2(src[i], hi, lo);
    size_t base = (size_t)row * (NH_ * KQK) + (size_t)h * KQK;
    if (variant == 0) {
        dst[base + jh] = hi; dst[base + HD_ + jh] = lo; dst[base + 2 * HD_ + jh] = hi;
    } else {
        dst[base + jh] = hi; dst[base + HD_ + jh] = hi; dst[base + 2 * HD_ + jh] = lo;
    }
}

__global__ void split_vt_kernel(const float* __restrict__ V, __nv_bfloat16* __restrict__ dst) {
    __shared__ float tile[32][33];
    const int s0 = blockIdx.x * 32, j0 = blockIdx.y * 32;
    const int t = threadIdx.x;
#pragma unroll
    for (int e = 0; e < 4; e++) {
        int idx = t + 256 * e;
        int sl = idx >> 5, jl = idx & 31;
        tile[sl][jl] = V[(size_t)(s0 + sl) * H_ + j0 + jl];
    }
    __syncthreads();
#pragma unroll
    for (int e = 0; e < 4; e++) {
        int idx = t + 256 * e;
        int nl = idx >> 5, sl = idx & 31;
        int j = j0 + nl, s = s0 + sl;
        int h = j >> 9, n = j & (HD_ - 1);
        __nv_bfloat16 hi, lo;
        split2(tile[sl][nl], hi, lo);
        size_t base = ((size_t)h * HD_ + n) * KPV;
        dst[base + s] = hi; dst[base + S_ + s] = hi; dst[base + 2 * (size_t)S_ + s] = lo;
    }
}

// ===================== mask / semb / kvin ====================================
__global__ void mask_prep_kernel(const unsigned char* __restrict__ mraw) {
    __shared__ int flag;
    if (threadIdx.x == 0) flag = 0;
    __syncthreads();
    int local = 0;
    for (int i = threadIdx.x; i < S_; i += blockDim.x)
        if ((i & 3) && mraw[i]) local = 1;
    if (local) atomicOr(&flag, 1);
    __syncthreads();
    if (flag) {
        for (int i = threadIdx.x; i < S_; i += blockDim.x) g_maskb[i] = mraw[i] ? 1 : 0;
    } else {
        const int* mi = (const int*)mraw;
        for (int i = threadIdx.x; i < S_; i += blockDim.x) g_maskb[i] = mi[i] ? 1 : 0;
    }
}

__global__ void semb_kernel(const float* __restrict__ Ws, const float* __restrict__ sd,
                            const float* __restrict__ bsv) {
    int j = blockIdx.x * blockDim.x + threadIdx.x;
    if (j < H_) {
        float acc = bsv[j];
#pragma unroll
        for (int i = 0; i < DS_; i++) acc = fmaf(Ws[j * DS_ + i], sd[i], acc);
        g_semb[j] = acc;
    }
}

__global__ void kvin_kernel(const float* __restrict__ inp) {
    size_t idx = (size_t)blockIdx.x * blockDim.x + threadIdx.x;
    g_kvin[idx] = inp[idx] + g_semb[idx & (H_ - 1)];
}

// ===================== reductions / softmax / LN =============================
__device__ __forceinline__ float blk_red_max(float v, float* sh) {
    int tid = threadIdx.x;
#pragma unroll
    for (int o = 16; o > 0; o >>= 1) v = fmaxf(v, __shfl_xor_sync(0xffffffffu, v, o));
    if ((tid & 31) == 0) sh[tid >> 5] = v;
    __syncthreads();
    if (tid < 32) {
        float x = (tid < 8) ? sh[tid] : -FLT_MAX;
#pragma unroll
        for (int o = 4; o > 0; o >>= 1) x = fmaxf(x, __shfl_xor_sync(0xffffffffu, x, o));
        if (tid == 0) sh[0] = x;
    }
    __syncthreads();
    float r = sh[0];
    __syncthreads();
    return r;
}
__device__ __forceinline__ float blk_red_sum(float v, float* sh) {
    int tid = threadIdx.x;
#pragma unroll
    for (int o = 16; o > 0; o >>= 1) v += __shfl_xor_sync(0xffffffffu, v, o);
    if ((tid & 31) == 0) sh[tid >> 5] = v;
    __syncthreads();
    if (tid < 32) {
        float x = (tid < 8) ? sh[tid] : 0.f;
#pragma unroll
        for (int o = 4; o > 0; o >>= 1) x += __shfl_xor_sync(0xffffffffu, x, o);
        if (tid == 0) sh[0] = x;
    }
    __syncthreads();
    float r = sh[0];
    __syncthreads();
    return r;
}

__global__ void softmax_split_kernel() {
    __shared__ float sh[8];
    __shared__ float srow[S_];
    const int q = blockIdx.x, tid = threadIdx.x;
    const float* row = g_logits + (size_t)q * S_;

    float m = -FLT_MAX;
    for (int i = tid; i < S_; i += 256) {
        float x = row[i];
        srow[i] = x;
        m = fmaxf(m, x);
    }
    m = blk_red_max(m, sh);

    float sum = 0.f;
    for (int i = tid; i < S_; i += 256) {
        float x = srow[i];
        float e = (x == -FLT_MAX) ? 0.f : __expf(x - m);
        srow[i] = e;
        sum += e;
    }
    sum = blk_red_sum(sum, sh);
    float inv = 1.f / sum;

    __nv_bfloat16* dst = g_Ps + (size_t)q * KPV;
    for (int i = tid; i < S_; i += 256) {
        float p = srow[i] * inv;
        __nv_bfloat16 hi, lo;
        split2(p, hi, lo);
        dst[i] = hi; dst[S_ + i] = lo; dst[2 * S_ + i] = hi;
    }
}

__global__ void ln_kernel(const float* __restrict__ inp, const float* __restrict__ lnw,
                          const float* __restrict__ lnb, float* __restrict__ out) {
    __shared__ float sh[8];
    const int s = blockIdx.x, tid = threadIdx.x;
    const float* o = g_out + (size_t)s * H_;
    const float* x = inp + (size_t)s * H_;

    float sum = 0.f, sq = 0.f;
    for (int i = tid; i < H_; i += 256) {
        float r = o[i] + x[i];
        sum += r; sq += r * r;
    }
    sum = blk_red_sum(sum, sh);
    sq  = blk_red_sum(sq, sh);
    float mu  = sum * (1.f / H_);
    float var = sq * (1.f / H_) - mu * mu;
    float inv = rsqrtf(var + 1e-5f);
    for (int i = tid; i < H_; i += 256) {
        float r = o[i] + x[i];
        out[(size_t)s * H_ + i] = (r - mu) * inv * lnw[i] + lnb[i];
    }
}

// ===================== launch ================================================
extern "C" void kernel_launch(void* const* d_in, const int* in_sizes, int n_in,
                              void* d_out, int out_size) {
    const float*         inputs = (const float*)d_in[0];
    const float*         sd     = (const float*)d_in[1];
    const unsigned char* mraw   = (const unsigned char*)d_in[2];
    const float*         Wq     = (const float*)d_in[3];
    const float*         Wk     = (const float*)d_in[4];
    const float*         Wv     = (const float*)d_in[5];
    const float*         Wo     = (const float*)d_in[6];
    const float*         Ws     = (const float*)d_in[7];
    const float*         bsv    = (const float*)d_in[8];
    const float*         lnw    = (const float*)d_in[9];
    const float*         lnb    = (const float*)d_in[10];
    float*               out    = (float*)d_out;

    float *pQ, *pK, *pV, *pKV, *pCtx, *pLog, *pOut;
    unsigned char* pMask;
    __nv_bfloat16 *pInsS, *pKvS, *pWqS, *pWkS, *pWvS, *pWoS, *pQs, *pKs, *pPs, *pVts, *pCtxS;
    cudaGetSymbolAddress((void**)&pQ,    g_Q);
    cudaGetSymbolAddress((void**)&pK,    g_K);
    cudaGetSymbolAddress((void**)&pV,    g_V);
    cudaGetSymbolAddress((void**)&pKV,   g_kvin);
    cudaGetSymbolAddress((void**)&pCtx,  g_ctx);
    cudaGetSymbolAddress((void**)&pLog,  g_logits);
    cudaGetSymbolAddress((void**)&pOut,  g_out);
    cudaGetSymbolAddress((void**)&pMask, g_maskb);
    cudaGetSymbolAddress((void**)&pInsS, g_ins_s);
    cudaGetSymbolAddress((void**)&pKvS,  g_kvin_s);
    cudaGetSymbolAddress((void**)&pWqS,  g_Wq_s);
    cudaGetSymbolAddress((void**)&pWkS,  g_Wk_s);
    cudaGetSymbolAddress((void**)&pWvS,  g_Wv_s);
    cudaGetSymbolAddress((void**)&pWoS,  g_Wo_s);
    cudaGetSymbolAddress((void**)&pQs,   g_Qs);
    cudaGetSymbolAddress((void**)&pKs,   g_Ks);
    cudaGetSymbolAddress((void**)&pPs,   g_Ps);
    cudaGetSymbolAddress((void**)&pVts,  g_Vts);
    cudaGetSymbolAddress((void**)&pCtxS, g_ctxs);

    cudaFuncSetAttribute(bf16_gemm_kernel, cudaFuncAttributeMaxDynamicSharedMemorySize, GEMM_SMEM);

    const float inv_sqrt_hd = 1.0f / sqrtf((float)HD_);

    // 0. mask canonicalization + static embedding + kv input
    mask_prep_kernel<<<1, 256>>>(mraw);
    semb_kernel<<<4, 256>>>(Ws, sd, bsv);
    kvin_kernel<<<(S_ * H_) / 256, 256>>>(inputs);

    // 1. operand splits
    split_plain_kernel<<<(S_ * H_) / 256, 256>>>(inputs, pInsS, H_, 0);
    split_plain_kernel<<<(S_ * H_) / 256, 256>>>(pKV,    pKvS,  H_, 0);
    split_plain_kernel<<<(H_ * H_) / 256, 256>>>(Wq, pWqS, H_, 1);
    split_plain_kernel<<<(H_ * H_) / 256, 256>>>(Wk, pWkS, H_, 1);
    split_plain_kernel<<<(H_ * H_) / 256, 256>>>(Wv, pWvS, H_, 1);
    split_plain_kernel<<<(H_ * H_) / 256, 256>>>(Wo, pWoS, H_, 1);

    // 2. projections (tensor-core, split-K)
    dim3 gp(H_ / 128, S_ / 128);
    bf16_gemm_kernel<<<gp, 256, GEMM_SMEM>>>(pInsS, K3, pWqS, K3, pQ, H_, K3, 1.f, nullptr);
    bf16_gemm_kernel<<<gp, 256, GEMM_SMEM>>>(pKvS,  K3, pWkS, K3, pK, H_, K3, 1.f, nullptr);
    bf16_gemm_kernel<<<gp, 256, GEMM_SMEM>>>(pKvS,  K3, pWvS, K3, pV, H_, K3, 1.f, nullptr);

    // 3. head splits
    split_heads_kernel<<<(S_ * H_) / 256, 256>>>(pQ, pQs, 0);
    split_heads_kernel<<<(S_ * H_) / 256, 256>>>(pK, pKs, 1);
    split_vt_kernel<<<dim3(S_ / 32, H_ / 32), 256>>>(pV, pVts);

    // 4. attention per head
    for (int h = 0; h < NH_; h++) {
        dim3 gl(S_ / 128, S_ / 128);
        bf16_gemm_kernel<<<gl, 256, GEMM_SMEM>>>(
            pQs + (size_t)h * KQK, NH_ * KQK,
            pKs + (size_t)h * KQK, NH_ * KQK,
            pLog, S_, KQK, inv_sqrt_hd, (h == 0) ? pMask : nullptr);
        softmax_split_kernel<<<S_, 256>>>();
        dim3 gv(HD_ / 128, S_ / 128);
        bf16_gemm_kernel<<<gv, 256, GEMM_SMEM>>>(
            pPs, KPV,
            pVts + (size_t)h * HD_ * KPV, KPV,
            pCtx + (size_t)h * HD_, H_, KPV, 1.f, nullptr);
    }

    // 5. output projection + residual LayerNorm
    split_plain_kernel<<<(S_ * H_) / 256, 256>>>(pCtx, pCtxS, H_, 0);
    bf16_gemm_kernel<<<gp, 256, GEMM_SMEM>>>(pCtxS, K3, pWoS, K3, pOut, H_, K3, 1.f, nullptr);
    ln_kernel<<<S_, 256>>>(inputs, lnw, lnb, out);
}

// round 5
// speedup vs baseline: 3.2915x; 1.1289x over previous
#include <cuda_runtime.h>
#include <cuda_bf16.h>
#include <math.h>
#include <float.h>
#include <stdint.h>

#define S_  4096
#define H_  1024
#define NH_ 2
#define HD_ 512
#define DS_ 64
#define K3  (3 * H_)    // 3072
#define KQK (3 * HD_)   // 1536
#define KPV (3 * S_)    // 12288

// ---------------- scratch (device globals; no allocations allowed) ----------
__device__ float g_semb[H_];
__device__ float g_Q[(size_t)S_ * H_];
__device__ float g_K[(size_t)S_ * H_];
__device__ float g_V[(size_t)S_ * H_];
__device__ float g_ctx[(size_t)S_ * H_];
__device__ float g_logits2[(size_t)NH_ * S_ * S_];
__device__ float g_out[(size_t)S_ * H_];
__device__ unsigned char g_maskb[S_];

__device__ __nv_bfloat16 g_ins_s [(size_t)S_ * K3];
__device__ __nv_bfloat16 g_kvin_s[(size_t)S_ * K3];
__device__ __nv_bfloat16 g_Wq_s[(size_t)H_ * K3];
__device__ __nv_bfloat16 g_Wk_s[(size_t)H_ * K3];
__device__ __nv_bfloat16 g_Wv_s[(size_t)H_ * K3];
__device__ __nv_bfloat16 g_Wo_s[(size_t)H_ * K3];
__device__ __nv_bfloat16 g_Qs[(size_t)S_ * NH_ * KQK];
__device__ __nv_bfloat16 g_Ks[(size_t)S_ * NH_ * KQK];
__device__ __nv_bfloat16 g_Ps2[(size_t)NH_ * S_ * KPV];
__device__ __nv_bfloat16 g_Vts[(size_t)NH_ * HD_ * KPV];
__device__ __nv_bfloat16 g_ctxs[(size_t)S_ * K3];

// ===================== helpers ===============================================
__device__ __forceinline__ uint32_t smem_u32(const void* p) {
    uint32_t a;
    asm("{ .reg .u64 t; cvta.to.shared.u64 t, %1; cvt.u32.u64 %0, t; }" : "=r"(a) : "l"(p));
    return a;
}
#define CP_ASYNC16(dst, src) \
    asm volatile("cp.async.cg.shared.global [%0], [%1], 16;" :: "r"(dst), "l"(src))
#define CP_COMMIT() asm volatile("cp.async.commit_group;")
#define CP_WAIT(n)  asm volatile("cp.async.wait_group %0;" :: "n"(n))

__device__ __forceinline__ void ldsm_x4(uint32_t& r0, uint32_t& r1, uint32_t& r2, uint32_t& r3,
                                        uint32_t addr) {
    asm volatile("ldmatrix.sync.aligned.m8n8.x4.shared.b16 {%0,%1,%2,%3}, [%4];"
                 : "=r"(r0), "=r"(r1), "=r"(r2), "=r"(r3) : "r"(addr));
}
__device__ __forceinline__ void mma_16816(float* c, const uint32_t* a, uint32_t b0, uint32_t b1) {
    asm volatile("mma.sync.aligned.m16n8k16.row.col.f32.bf16.bf16.f32 "
                 "{%0,%1,%2,%3}, {%4,%5,%6,%7}, {%8,%9}, {%0,%1,%2,%3};"
                 : "+f"(c[0]), "+f"(c[1]), "+f"(c[2]), "+f"(c[3])
                 : "r"(a[0]), "r"(a[1]), "r"(a[2]), "r"(a[3]), "r"(b0), "r"(b1));
}

// smem tile: 128 rows x 64 bf16 (128B/row), XOR swizzle on 16B chunks
__device__ __forceinline__ uint32_t toff(int r, int c8) {
    return (uint32_t)(r * 128 + ((c8 ^ (r & 7)) << 4));
}

// ===================== bf16 HMMA GEMM ========================================
// C[M,N](fp32) = alpha * A[M,Kp](bf16,K-major) . B[N,Kp]^T(bf16,K-major)
// CTA tile 128x128, BK=64, 4 warps (64x64 warp tile), 3-stage cp.async.
// gridDim.z batches heads: A/B/C advance by per-z element strides; mask applies
// only to z==0.
#define GEMM_SMEM (3 * 32768)

__global__ __launch_bounds__(128, 2)
void bf16_gemm_kernel(const __nv_bfloat16* __restrict__ A, int lda, size_t sAz,
                      const __nv_bfloat16* __restrict__ B, int ldb, size_t sBz,
                      float* __restrict__ C, int ldc, size_t sCz,
                      int Kp, float alpha,
                      const unsigned char* __restrict__ mask) {
    extern __shared__ char smem[];
    const uint32_t sb = smem_u32(smem);
    const int tid = threadIdx.x, lane = tid & 31, wid = tid >> 5;
    const int row0 = blockIdx.y * 128, col0 = blockIdx.x * 128;
    const int z = blockIdx.z;
    A += (size_t)z * sAz;  B += (size_t)z * sBz;  C += (size_t)z * sCz;
    const unsigned char* mk = (z == 0) ? mask : nullptr;

    const int wm = wid & 1, wn = wid >> 1;          // 2x2 warp grid
    const int m_base = wm * 64, n_base = wn * 64;   // 64x64 per warp

    // cp.async mapping
    const int lr = tid >> 3, lc = tid & 7;          // 16 rows per pass, 8 chunks

    // ldmatrix lane patterns
    const int g = lane >> 3, ri = lane & 7;
    const int a_r = ri + ((g & 1) << 3), a_c = g >> 1;
    const int b_r = ri + ((g >> 1) << 3), b_c = g & 1;

    float acc[4][8][4];
#pragma unroll
    for (int i = 0; i < 4; i++)
#pragma unroll
        for (int j = 0; j < 8; j++)
#pragma unroll
            for (int k = 0; k < 4; k++) acc[i][j][k] = 0.f;

    const int NS = Kp >> 6;

    auto load_stage = [&](int s) {
        const int k0 = s << 6;
        const uint32_t ba = sb + (s % 3) * 32768;
        const uint32_t bb = ba + 16384;
#pragma unroll
        for (int i = 0; i < 8; i++) {
            int r = lr + 16 * i;
            const __nv_bfloat16* gA = A + (size_t)(row0 + r) * lda + k0 + lc * 8;
            const __nv_bfloat16* gB = B + (size_t)(col0 + r) * ldb + k0 + lc * 8;
            uint32_t so = toff(r, lc);
            CP_ASYNC16(ba + so, gA);
            CP_ASYNC16(bb + so, gB);
        }
        CP_COMMIT();
    };

    load_stage(0);
    load_stage(1);

    for (int s = 0; s < NS; s++) {
        if (s == NS - 1) { CP_WAIT(0); } else { CP_WAIT(1); }
        __syncthreads();

        const uint32_t ba = sb + (s % 3) * 32768;
        const uint32_t bb = ba + 16384;
#pragma unroll
        for (int ks = 0; ks < 4; ks++) {
            const int c8k = ks << 1;
            uint32_t afr[4][4];
#pragma unroll
            for (int mi = 0; mi < 4; mi++)
                ldsm_x4(afr[mi][0], afr[mi][1], afr[mi][2], afr[mi][3],
                        ba + toff(m_base + mi * 16 + a_r, c8k + a_c));
            uint32_t bfr[4][4];
#pragma unroll
            for (int p = 0; p < 4; p++)
                ldsm_x4(bfr[p][0], bfr[p][1], bfr[p][2], bfr[p][3],
                        bb + toff(n_base + p * 16 + b_r, c8k + b_c));
#pragma unroll
            for (int mi = 0; mi < 4; mi++)
#pragma unroll
                for (int nj = 0; nj < 8; nj++) {
                    const uint32_t* bp = bfr[nj >> 1];
                    if (nj & 1) mma_16816(acc[mi][nj], afr[mi], bp[2], bp[3]);
                    else        mma_16816(acc[mi][nj], afr[mi], bp[0], bp[1]);
                }
        }
        // 3-buffer rotation: stage s+2 writes buffer (s+2)%3, disjoint from the
        // buffer read this iteration -> no second barrier needed.
        if (s + 2 < NS) load_stage(s + 2);
    }

    // epilogue: fused alpha + mask, float2 stores
    const int er = lane >> 2, ec = (lane & 3) << 1;
#pragma unroll
    for (int mi = 0; mi < 4; mi++) {
#pragma unroll
        for (int nj = 0; nj < 8; nj++) {
            int row = row0 + m_base + mi * 16 + er;
            int col = col0 + n_base + nj * 8 + ec;
            float2 v0, v1;
            v0.x = acc[mi][nj][0] * alpha; v0.y = acc[mi][nj][1] * alpha;
            v1.x = acc[mi][nj][2] * alpha; v1.y = acc[mi][nj][3] * alpha;
            if (mk != nullptr) {
                unsigned char m0 = mk[col], m1 = mk[col + 1];
                if (!m0) { v0.x = -FLT_MAX; v1.x = -FLT_MAX; }
                if (!m1) { v0.y = -FLT_MAX; v1.y = -FLT_MAX; }
            }
            *reinterpret_cast<float2*>(C + (size_t)row * ldc + col) = v0;
            *reinterpret_cast<float2*>(C + (size_t)(row + 8) * ldc + col) = v1;
        }
    }
}

// ===================== split kernels =========================================
__device__ __forceinline__ void split2(float x, __nv_bfloat16& hi, __nv_bfloat16& lo) {
    hi = __float2bfloat16(x);
    lo = __float2bfloat16(x - __bfloat162float(hi));
}

// variant 0 (A side): [hi | lo | hi] ; variant 1 (B side): [hi | hi | lo]
// addsemb: add g_semb[col % H] before splitting (kv input fusion)
__global__ void split_plain_kernel(const float* __restrict__ src, __nv_bfloat16* __restrict__ dst,
                                   int K, int variant, int addsemb) {
    size_t i = (size_t)blockIdx.x * blockDim.x + threadIdx.x;
    int row = (int)(i / K), col = (int)(i % K);
    float x = src[i];
    if (addsemb) x += g_semb[col];
    __nv_bfloat16 hi, lo;
    split2(x, hi, lo);
    size_t base = (size_t)row * (3 * (size_t)K);
    if (variant == 0) {
        dst[base + col] = hi; dst[base + K + col] = lo; dst[base + 2 * (size_t)K + col] = hi;
    } else {
        dst[base + col] = hi; dst[base + K + col] = hi; dst[base + 2 * (size_t)K + col] = lo;
    }
}

__global__ void split_heads_kernel(const float* __restrict__ src, __nv_bfloat16* __restrict__ dst,
                                   int variant) {
    size_t i = (size_t)blockIdx.x * blockDim.x + threadIdx.x;
    int row = (int)(i >> 10), j = (int)(i & (H_ - 1));
    int h = j >> 9, jh = j & (HD_ - 1);
    __nv_bfloat16 hi, lo;
    split2(src[i], hi, lo);
    size_t base = (size_t)row * (NH_ * KQK) + (size_t)h * KQK;
    if (variant == 0) {
        dst[base + jh] = hi; dst[base + HD_ + jh] = lo; dst[base + 2 * HD_ + jh] = hi;
    } else {
        dst[base + jh] = hi; dst[base + HD_ + jh] = hi; dst[base + 2 * HD_ + jh] = lo;
    }
}

__global__ void split_vt_kernel(const float* __restrict__ V, __nv_bfloat16* __restrict__ dst) {
    __shared__ float tile[32][33];
    const int s0 = blockIdx.x * 32, j0 = blockIdx.y * 32;
    const int t = threadIdx.x;
#pragma unroll
    for (int e = 0; e < 4; e++) {
        int idx = t + 256 * e;
        int sl = idx >> 5, jl = idx & 31;
        tile[sl][jl] = V[(size_t)(s0 + sl) * H_ + j0 + jl];
    }
    __syncthreads();
#pragma unroll
    for (int e = 0; e < 4; e++) {
        int idx = t + 256 * e;
        int nl = idx >> 5, sl = idx & 31;
        int j = j0 + nl, s = s0 + sl;
        int h = j >> 9, n = j & (HD_ - 1);
        __nv_bfloat16 hi, lo;
        split2(tile[sl][nl], hi, lo);
        size_t base = ((size_t)h * HD_ + n) * KPV;
        dst[base + s] = hi; dst[base + S_ + s] = hi; dst[base + 2 * (size_t)S_ + s] = lo;
    }
}

// ===================== mask / semb ===========================================
__global__ void mask_prep_kernel(const unsigned char* __restrict__ mraw) {
    __shared__ int flag;
    if (threadIdx.x == 0) flag = 0;
    __syncthreads();
    int local = 0;
    for (int i = threadIdx.x; i < S_; i += blockDim.x)
        if ((i & 3) && mraw[i]) local = 1;
    if (local) atomicOr(&flag, 1);
    __syncthreads();
    if (flag) {
        for (int i = threadIdx.x; i < S_; i += blockDim.x) g_maskb[i] = mraw[i] ? 1 : 0;
    } else {
        const int* mi = (const int*)mraw;
        for (int i = threadIdx.x; i < S_; i += blockDim.x) g_maskb[i] = mi[i] ? 1 : 0;
    }
}

__global__ void semb_kernel(const float* __restrict__ Ws, const float* __restrict__ sd,
                            const float* __restrict__ bsv) {
    int j = blockIdx.x * blockDim.x + threadIdx.x;
    if (j < H_) {
        float acc = bsv[j];
#pragma unroll
        for (int i = 0; i < DS_; i++) acc = fmaf(Ws[j * DS_ + i], sd[i], acc);
        g_semb[j] = acc;
    }
}

// ===================== reductions / softmax / LN =============================
__device__ __forceinline__ float blk_red_max(float v, float* sh) {
    int tid = threadIdx.x;
#pragma unroll
    for (int o = 16; o > 0; o >>= 1) v = fmaxf(v, __shfl_xor_sync(0xffffffffu, v, o));
    if ((tid & 31) == 0) sh[tid >> 5] = v;
    __syncthreads();
    if (tid < 32) {
        float x = (tid < 8) ? sh[tid] : -FLT_MAX;
#pragma unroll
        for (int o = 4; o > 0; o >>= 1) x = fmaxf(x, __shfl_xor_sync(0xffffffffu, x, o));
        if (tid == 0) sh[0] = x;
    }
    __syncthreads();
    float r = sh[0];
    __syncthreads();
    return r;
}
__device__ __forceinline__ float blk_red_sum(float v, float* sh) {
    int tid = threadIdx.x;
#pragma unroll
    for (int o = 16; o > 0; o >>= 1) v += __shfl_xor_sync(0xffffffffu, v, o);
    if ((tid & 31) == 0) sh[tid >> 5] = v;
    __syncthreads();
    if (tid < 32) {
        float x = (tid < 8) ? sh[tid] : 0.f;
#pragma unroll
        for (int o = 4; o > 0; o >>= 1) x += __shfl_xor_sync(0xffffffffu, x, o);
        if (tid == 0) sh[0] = x;
    }
    __syncthreads();
    float r = sh[0];
    __syncthreads();
    return r;
}

__global__ void softmax_split_kernel() {
    __shared__ float sh[8];
    __shared__ float srow[S_];
    const int q = blockIdx.x, h = blockIdx.y, tid = threadIdx.x;
    const float* row = g_logits2 + ((size_t)h * S_ + q) * S_;

    float m = -FLT_MAX;
    for (int i = tid; i < S_; i += 256) {
        float x = row[i];
        srow[i] = x;
        m = fmaxf(m, x);
    }
    m = blk_red_max(m, sh);

    float sum = 0.f;
    for (int i = tid; i < S_; i += 256) {
        float x = srow[i];
        float e = (x == -FLT_MAX) ? 0.f : __expf(x - m);
        srow[i] = e;
        sum += e;
    }
    sum = blk_red_sum(sum, sh);
    float inv = 1.f / sum;

    __nv_bfloat16* dst = g_Ps2 + ((size_t)h * S_ + q) * KPV;
    for (int i = tid; i < S_; i += 256) {
        float p = srow[i] * inv;
        __nv_bfloat16 hi, lo;
        split2(p, hi, lo);
        dst[i] = hi; dst[S_ + i] = lo; dst[2 * S_ + i] = hi;
    }
}

__global__ void ln_kernel(const float* __restrict__ inp, const float* __restrict__ lnw,
                          const float* __restrict__ lnb, float* __restrict__ out) {
    __shared__ float sh[8];
    const int s = blockIdx.x, tid = threadIdx.x;
    const float* o = g_out + (size_t)s * H_;
    const float* x = inp + (size_t)s * H_;

    float sum = 0.f, sq = 0.f;
    for (int i = tid; i < H_; i += 256) {
        float r = o[i] + x[i];
        sum += r; sq += r * r;
    }
    sum = blk_red_sum(sum, sh);
    sq  = blk_red_sum(sq, sh);
    float mu  = sum * (1.f / H_);
    float var = sq * (1.f / H_) - mu * mu;
    float inv = rsqrtf(var + 1e-5f);
    for (int i = tid; i < H_; i += 256) {
        float r = o[i] + x[i];
        out[(size_t)s * H_ + i] = (r - mu) * inv * lnw[i] + lnb[i];
    }
}

// ===================== launch ================================================
extern "C" void kernel_launch(void* const* d_in, const int* in_sizes, int n_in,
                              void* d_out, int out_size) {
    const float*         inputs = (const float*)d_in[0];
    const float*         sd     = (const float*)d_in[1];
    const unsigned char* mraw   = (const unsigned char*)d_in[2];
    const float*         Wq     = (const float*)d_in[3];
    const float*         Wk     = (const float*)d_in[4];
    const float*         Wv     = (const float*)d_in[5];
    const float*         Wo     = (const float*)d_in[6];
    const float*         Ws     = (const float*)d_in[7];
    const float*         bsv    = (const float*)d_in[8];
    const float*         lnw    = (const float*)d_in[9];
    const float*         lnb    = (const float*)d_in[10];
    float*               out    = (float*)d_out;

    float *pQ, *pK, *pV, *pCtx, *pLog, *pOut;
    unsigned char* pMask;
    __nv_bfloat16 *pInsS, *pKvS, *pWqS, *pWkS, *pWvS, *pWoS, *pQs, *pKs, *pPs, *pVts, *pCtxS;
    cudaGetSymbolAddress((void**)&pQ,    g_Q);
    cudaGetSymbolAddress((void**)&pK,    g_K);
    cudaGetSymbolAddress((void**)&pV,    g_V);
    cudaGetSymbolAddress((void**)&pCtx,  g_ctx);
    cudaGetSymbolAddress((void**)&pLog,  g_logits2);
    cudaGetSymbolAddress((void**)&pOut,  g_out);
    cudaGetSymbolAddress((void**)&pMask, g_maskb);
    cudaGetSymbolAddress((void**)&pInsS, g_ins_s);
    cudaGetSymbolAddress((void**)&pKvS,  g_kvin_s);
    cudaGetSymbolAddress((void**)&pWqS,  g_Wq_s);
    cudaGetSymbolAddress((void**)&pWkS,  g_Wk_s);
    cudaGetSymbolAddress((void**)&pWvS,  g_Wv_s);
    cudaGetSymbolAddress((void**)&pWoS,  g_Wo_s);
    cudaGetSymbolAddress((void**)&pQs,   g_Qs);
    cudaGetSymbolAddress((void**)&pKs,   g_Ks);
    cudaGetSymbolAddress((void**)&pPs,   g_Ps2);
    cudaGetSymbolAddress((void**)&pVts,  g_Vts);
    cudaGetSymbolAddress((void**)&pCtxS, g_ctxs);

    cudaFuncSetAttribute(bf16_gemm_kernel, cudaFuncAttributeMaxDynamicSharedMemorySize, GEMM_SMEM);

    const float inv_sqrt_hd = 1.0f / sqrtf((float)HD_);
    dim3 gp(H_ / 128, S_ / 128, 1);

    // launches 1-5 (ncu profiles launch #6 => first projection GEMM)
    semb_kernel<<<4, 256>>>(Ws, sd, bsv);                                   // 1
    mask_prep_kernel<<<1, 256>>>(mraw);                                     // 2
    split_plain_kernel<<<(S_ * H_) / 256, 256>>>(inputs, pInsS, H_, 0, 0);  // 3
    split_plain_kernel<<<(S_ * H_) / 256, 256>>>(inputs, pKvS,  H_, 0, 1);  // 4 (kv fused)
    split_plain_kernel<<<(H_ * H_) / 256, 256>>>(Wq, pWqS, H_, 1, 0);       // 5
    bf16_gemm_kernel<<<gp, 128, GEMM_SMEM>>>(pInsS, K3, 0, pWqS, K3, 0,
                                             pQ, H_, 0, K3, 1.f, nullptr);  // 6 <- profiled
    split_plain_kernel<<<(H_ * H_) / 256, 256>>>(Wk, pWkS, H_, 1, 0);
    bf16_gemm_kernel<<<gp, 128, GEMM_SMEM>>>(pKvS, K3, 0, pWkS, K3, 0,
                                             pK, H_, 0, K3, 1.f, nullptr);
    split_plain_kernel<<<(H_ * H_) / 256, 256>>>(Wv, pWvS, H_, 1, 0);
    bf16_gemm_kernel<<<gp, 128, GEMM_SMEM>>>(pKvS, K3, 0, pWvS, K3, 0,
                                             pV, H_, 0, K3, 1.f, nullptr);
    split_plain_kernel<<<(H_ * H_) / 256, 256>>>(Wo, pWoS, H_, 1, 0);

    // head splits
    split_heads_kernel<<<(S_ * H_) / 256, 256>>>(pQ, pQs, 0);
    split_heads_kernel<<<(S_ * H_) / 256, 256>>>(pK, pKs, 1);
    split_vt_kernel<<<dim3(S_ / 32, H_ / 32), 256>>>(pV, pVts);

    // attention: both heads batched via gridDim.z
    dim3 gl(S_ / 128, S_ / 128, NH_);
    bf16_gemm_kernel<<<gl, 128, GEMM_SMEM>>>(
        pQs, NH_ * KQK, KQK,
        pKs, NH_ * KQK, KQK,
        pLog, S_, (size_t)S_ * S_,
        KQK, inv_sqrt_hd, pMask);
    softmax_split_kernel<<<dim3(S_, NH_), 256>>>();
    dim3 gv(HD_ / 128, S_ / 128, NH_);
    bf16_gemm_kernel<<<gv, 128, GEMM_SMEM>>>(
        pPs, KPV, (size_t)S_ * KPV,
        pVts, KPV, (size_t)HD_ * KPV,
        pCtx, H_, HD_,
        KPV, 1.f, nullptr);

    // output projection + residual LayerNorm
    split_plain_kernel<<<(S_ * H_) / 256, 256>>>(pCtx, pCtxS, H_, 0, 0);
    bf16_gemm_kernel<<<gp, 128, GEMM_SMEM>>>(pCtxS, K3, 0, pWoS, K3, 0,
                                             pOut, H_, 0, K3, 1.f, nullptr);
    ln_kernel<<<S_, 256>>>(inputs, lnw, lnb, out);
}